// round 12
// baseline (speedup 1.0000x reference)
#include <cuda_runtime.h>
#include <stdint.h>
#include <math.h>

#define H   4096
#define HS  64
#define NH  64
#define TM  64
#define TD  128
#define EPS 1e-5f
#define CHUNK 256              // floats per row-chunk (1KB/row-chunk)
#define NCH   (H / CHUNK)      // 16 chunks
#define NSTG  3
#define NB123 128

// ---------------- scratch ----------------
__device__ __align__(16) float g_mix[5 * H];
__device__ __align__(16) float g_r[H];
__device__ __align__(16) float g_k[H];
__device__ __align__(16) float g_v[H];
__device__ __align__(16) float g_g[H];
__device__ __align__(16) float g_z128[TD];
__device__ __align__(16) float g_og[H];
__device__ __align__(16) float g_ypart[NB123][5 * TM];
__device__ int g_ctr[2];   // zero-init; last arriver resets each launch

__device__ __forceinline__ uint32_t smem_u32(const void* p) {
    return (uint32_t)__cvta_generic_to_shared(p);
}
__device__ __forceinline__ void cp16(uint32_t d, const void* s) {
    asm volatile("cp.async.cg.shared.global [%0], [%1], 16;" :: "r"(d), "l"(s));
}
__device__ __forceinline__ void cp_commit() {
    asm volatile("cp.async.commit_group;" ::: "memory");
}
template <int N>
__device__ __forceinline__ void cp_wait() {
    asm volatile("cp.async.wait_group %0;" :: "n"(N) : "memory");
}

// ---------------- K123: LN + maa-LoRA down + up, one kernel, one grid barrier ----------------
__global__ void __launch_bounds__(256) k123(
        const float* __restrict__ x,      const float* __restrict__ state1,
        const float* __restrict__ ln1w,   const float* __restrict__ ln1b,
        const float* __restrict__ tmx,    const float* __restrict__ tmaa,
        const float* __restrict__ w1,     const float* __restrict__ w2,
        float* __restrict__ out) {
    __shared__ float ssr[16];
    __shared__ float sxm[32], sxl[32], ssx[32];
    __shared__ float sty[5 * TM];
    int b = blockIdx.x, tid = threadIdx.x;   // 128 blocks x 256 threads
    int warp = tid >> 5, lane = tid & 31;

    // redundant LN stats per block (x is 16KB, L2-hot)
    float s = 0.f, q = 0.f;
#pragma unroll
    for (int i = 0; i < 16; i++) {
        float v = x[tid + i * 256];
        s += v; q += v * v;
    }
    for (int o = 16; o; o >>= 1) { s += __shfl_down_sync(~0u, s, o); q += __shfl_down_sync(~0u, q, o); }
    if (lane == 0) { ssr[warp] = s; ssr[warp + 8] = q; }
    __syncthreads();
    if (tid < 8) {
        float a = ssr[tid], c = ssr[tid + 8];
        for (int o = 4; o; o >>= 1) { a += __shfl_down_sync(0xff, a, o); c += __shfl_down_sync(0xff, c, o); }
        if (tid == 0) { ssr[0] = a; ssr[8] = c; }
    }
    __syncthreads();
    float mu = ssr[0] * (1.f / H);
    float var = ssr[8] * (1.f / H) - mu * mu;
    float inv = rsqrtf(var + EPS);

    int j0 = b * 32;                      // this block's 32-row slice
    if (tid < 32) {
        int idx = j0 + tid;
        float xl = (x[idx] - mu) * inv * ln1w[idx] + ln1b[idx];
        float sxv = state1[idx] - xl;
        sxl[tid] = xl; ssx[tid] = sxv;
        sxm[tid] = xl + sxv * tmx[idx];
        out[H + idx] = xl;                // output #2: xl
    }
    if (b == 0 && tid < TD) g_z128[tid] = 0.f;
    __syncthreads();

    // y320 partial over this block's 32 rows
    for (int c = tid; c < 320; c += 256) {
        float acc = 0.f;
#pragma unroll 8
        for (int j = 0; j < 32; j++)
            acc += sxm[j] * w1[(j0 + j) * 320 + c];
        g_ypart[b][c] = acc;
    }

    // ---- grid barrier (128 blocks, all resident) ----
    __syncthreads();
    if (tid == 0) {
        __threadfence();
        atomicAdd(&g_ctr[0], 1);
        while (*((volatile int*)&g_ctr[0]) < NB123) __nanosleep(64);
        __threadfence();
    }
    __syncthreads();

    // reduce partials + tanh
    for (int c = tid; c < 320; c += 256) {
        float y = 0.f;
#pragma unroll 8
        for (int bb = 0; bb < NB123; bb++) y += g_ypart[bb][c];
        sty[c] = tanhf(y);
    }
    __syncthreads();

    // mixes for this block's h-slice, all 5 f (160 work items)
    if (tid < 160) {
        int f = tid >> 5, hl = tid & 31;
        int h = j0 + hl;
        const float* base = w2 + (size_t)f * TM * H + h;
        float acc = 0.f;
#pragma unroll
        for (int t = 0; t < TM; t++) acc += sty[f * TM + t] * base[(size_t)t * H];
        g_mix[f * H + h] = sxl[hl] + ssx[hl] * (acc + tmaa[f * H + h]);
    }

    // ---- arrive + last-block counter reset (leaves zeros for next replay) ----
    __syncthreads();
    if (tid == 0) {
        __threadfence();
        int v = atomicAdd(&g_ctr[1], 1);
        if (v == NB123 - 1) { g_ctr[0] = 0; g_ctr[1] = 0; }
    }
}

// ---------------- K4: 4 big GEMVs (per-warp barrier-free cp.async pipeline) ----------------
__global__ void __launch_bounds__(256) k4_gemv4(
        const float* __restrict__ Wr, const float* __restrict__ Wk,
        const float* __restrict__ Wv, const float* __restrict__ Wg,
        const float* __restrict__ dw1) {
    __shared__ float sv[H];                        // 16KB vector tile
    __shared__ float stage[NSTG][8][CHUNK];        // 3 x 8KB, per-warp slices
    __shared__ float sh[256];

    if (blockIdx.x >= 2048) {
        cudaGridDependencySynchronize();
        // decay stage 1: z128 = mw @ decay_w1 (4096 x 128), 16 blocks x 256 rows
        int bb = blockIdx.x - 2048;
        int j0 = bb * 256;
        int t = threadIdx.x & 127;
        int sub = threadIdx.x >> 7;
        float acc = 0.f;
        for (int j = j0 + sub; j < j0 + 256; j += 2)
            acc += g_mix[j] * dw1[j * TD + t];   // mw = mix[0]
        sh[threadIdx.x] = acc;
        __syncthreads();
        if (sub == 0) atomicAdd(&g_z128[t], sh[t] + sh[t + 128]);
        return;
    }

    int mat = blockIdx.x >> 9;                   // 512 blocks per matrix
    const float* W; const float* vec;
    if (mat == 0)      { W = Wr; vec = g_mix + 3 * H; }   // r <- mr
    else if (mat == 1) { W = Wk; vec = g_mix + 1 * H; }   // k <- mk
    else if (mat == 2) { W = Wv; vec = g_mix + 2 * H; }   // v <- mv
    else               { W = Wg; vec = g_mix + 4 * H; }   // g <- mg

    int tid = threadIdx.x;
    int warp = tid >> 5, lane = tid & 31;
    int row = (blockIdx.x & 511) * 8 + warp;
    const float* Wrow = W + (size_t)row * H;     // this warp's row

    uint32_t sdst[NSTG];
#pragma unroll
    for (int s = 0; s < NSTG; s++)
        sdst[s] = smem_u32(&stage[s][warp][0]) + lane * 16;

    // prologue: weights are input-independent — issue BEFORE the PDL sync
#pragma unroll
    for (int s = 0; s < NSTG; s++) {
        const float4* src = (const float4*)(Wrow + s * CHUNK);
        cp16(sdst[s],            src + lane);
        cp16(sdst[s] + 32 * 16,  src + lane + 32);
        cp_commit();
    }

    cudaGridDependencySynchronize();

    // stage the vector (depends on K123); one barrier total
    {
        const float4* V4 = (const float4*)vec;
        float4* S4 = (float4*)sv;
#pragma unroll
        for (int i = 0; i < 4; i++)
            S4[tid + i * 256] = V4[tid + i * 256];
    }
    __syncthreads();

    float acc = 0.f;
#pragma unroll
    for (int c = 0; c < NCH; c++) {
        if (c < NCH - 2)       cp_wait<NSTG - 1>();
        else if (c == NCH - 2) cp_wait<1>();
        else                   cp_wait<0>();
        // lane reads exactly the slots it issued — no barrier needed
        const float4* SB = (const float4*)&stage[c % NSTG][warp][0];
        const float4* SV = (const float4*)&sv[c * CHUNK];
        float4 w0 = SB[lane],       u0 = SV[lane];
        float4 w1_ = SB[lane + 32], u1 = SV[lane + 32];
        acc += w0.x * u0.x + w0.y * u0.y + w0.z * u0.z + w0.w * u0.w;
        acc += w1_.x * u1.x + w1_.y * u1.y + w1_.z * u1.z + w1_.w * u1.w;
        if (c + NSTG < NCH) {
            const float4* src = (const float4*)(Wrow + (c + NSTG) * CHUNK);
            cp16(sdst[c % NSTG],           src + lane);
            cp16(sdst[c % NSTG] + 32 * 16, src + lane + 32);
            cp_commit();
        }
    }

    for (int o = 16; o; o >>= 1) acc += __shfl_down_sync(~0u, acc, o);
    if (lane == 0) {
        if (mat == 0)      g_r[row] = acc;
        else if (mat == 1) g_k[row] = acc;
        else if (mat == 2) g_v[row] = acc;
        else               g_g[row] = acc / (1.f + expf(-acc)); // silu
    }
}

// ---------------- K5: per-head decay/wkv/state/norm (256 threads/head) ----------------
__global__ void k5_heads(const float* __restrict__ state2,
                         const float* __restrict__ dw2,
                         const float* __restrict__ tdec,
                         const float* __restrict__ tfirst,
                         const float* __restrict__ lnxw,
                         const float* __restrict__ lnxb,
                         float* __restrict__ out) {
    cudaGridDependencySynchronize();
    int h = blockIdx.x;                 // 64 heads
    int tid = threadIdx.x;              // 256 threads
    int j = tid & 63;                   // column within head
    int p = tid >> 6;                   // 0..3 partition
    const float* s2 = state2 + (size_t)h * HS * HS;

    __shared__ float tz[TD], sr[HS], sk[HS], std_[HS], red[HS];
    __shared__ float part[4][HS];

    if (tid < TD) tz[tid] = tanhf(g_z128[tid]);
    __syncthreads();

    int gi = h * HS + j;

    float dacc = 0.f;
#pragma unroll
    for (int t = p * 32; t < p * 32 + 32; t++)
        dacc += tz[t] * dw2[(size_t)t * H + gi];
    part[p][j] = dacc;
    __syncthreads();
    if (p == 0) {
        float d = part[0][j] + part[1][j] + part[2][j] + part[3][j] + tdec[gi];
        d = fminf(fmaxf(d, -9.72f), 2.27f);
        std_[j] = expf(-expf(d));
        float rs = g_r[gi], ks = g_k[gi];
        sr[j] = rs; sk[j] = ks;
        red[j] = rs * ks * tfirst[gi];
    }
    __syncthreads();

    float a = 0.f;
#pragma unroll
    for (int t = 0; t < HS; t++) a += red[t];   // broadcast reads

    float vs = g_v[gi];
    float* s2o = out + 2 * H + (size_t)h * HS * HS;   // output #3: state2_out
    float acc2 = 0.f;
#pragma unroll
    for (int i = p * 16; i < p * 16 + 16; i++) {
        float s2v = s2[i * HS + j];
        acc2 += sr[i] * s2v;
        s2o[i * HS + j] = sk[i] * vs + s2v * std_[i];
    }
    part[p][j] = acc2;
    __syncthreads();

    if (p == 0) {
        float oj = a * vs + part[0][j] + part[1][j] + part[2][j] + part[3][j];
        red[j] = oj;
    }
    __syncthreads();
    if (p == 0) {
        float s = 0.f, q = 0.f;
#pragma unroll
        for (int t = 0; t < HS; t++) { float u = red[t]; s += u; q += u * u; }
        float mu = s * (1.f / HS);
        float var = q * (1.f / HS) - mu * mu;
        float nj = (red[j] - mu) * rsqrtf(var + EPS);
        g_og[gi] = (nj * lnxw[gi] + lnxb[gi]) * g_g[gi];
    }
}

// ---------------- K6: out = x + og @ Wo.T (per-warp barrier-free pipeline) ----------------
__global__ void __launch_bounds__(256) k6_out(const float* __restrict__ Wo,
                                              const float* __restrict__ x,
                                              float* __restrict__ out) {
    __shared__ float sv[H];
    __shared__ float stage[NSTG][8][CHUNK];
    int tid = threadIdx.x;
    int warp = tid >> 5, lane = tid & 31;
    int row = blockIdx.x * 8 + warp;
    const float* Wrow = Wo + (size_t)row * H;

    uint32_t sdst[NSTG];
#pragma unroll
    for (int s = 0; s < NSTG; s++)
        sdst[s] = smem_u32(&stage[s][warp][0]) + lane * 16;

#pragma unroll
    for (int s = 0; s < NSTG; s++) {
        const float4* src = (const float4*)(Wrow + s * CHUNK);
        cp16(sdst[s],            src + lane);
        cp16(sdst[s] + 32 * 16,  src + lane + 32);
        cp_commit();
    }

    cudaGridDependencySynchronize();

    {
        const float4* V4 = (const float4*)g_og;
        float4* S4 = (float4*)sv;
#pragma unroll
        for (int i = 0; i < 4; i++)
            S4[tid + i * 256] = V4[tid + i * 256];
    }
    __syncthreads();

    float acc = 0.f;
#pragma unroll
    for (int c = 0; c < NCH; c++) {
        if (c < NCH - 2)       cp_wait<NSTG - 1>();
        else if (c == NCH - 2) cp_wait<1>();
        else                   cp_wait<0>();
        const float4* SB = (const float4*)&stage[c % NSTG][warp][0];
        const float4* SV = (const float4*)&sv[c * CHUNK];
        float4 w0 = SB[lane],       u0 = SV[lane];
        float4 w1_ = SB[lane + 32], u1 = SV[lane + 32];
        acc += w0.x * u0.x + w0.y * u0.y + w0.z * u0.z + w0.w * u0.w;
        acc += w1_.x * u1.x + w1_.y * u1.y + w1_.z * u1.z + w1_.w * u1.w;
        if (c + NSTG < NCH) {
            const float4* src = (const float4*)(Wrow + (c + NSTG) * CHUNK);
            cp16(sdst[c % NSTG],           src + lane);
            cp16(sdst[c % NSTG] + 32 * 16, src + lane + 32);
            cp_commit();
        }
    }

    for (int o = 16; o; o >>= 1) acc += __shfl_down_sync(~0u, acc, o);
    if (lane == 0) out[row] = x[row] + acc;
}

// ---------------- launch helpers ----------------
template <typename... Args>
static void launch_pdl(void (*kern)(Args...), dim3 grid, dim3 block, Args... args) {
    cudaLaunchConfig_t cfg = {};
    cfg.gridDim = grid;
    cfg.blockDim = block;
    cfg.dynamicSmemBytes = 0;
    cfg.stream = 0;
    cudaLaunchAttribute attr[1];
    attr[0].id = cudaLaunchAttributeProgrammaticStreamSerialization;
    attr[0].val.programmaticStreamSerializationAllowed = 1;
    cfg.attrs = attr;
    cfg.numAttrs = 1;
    cudaLaunchKernelEx(&cfg, kern, args...);
}

extern "C" void kernel_launch(void* const* d_in, const int* in_sizes, int n_in,
                              void* d_out, int out_size) {
    const float* x       = (const float*)d_in[0];
    const float* state1  = (const float*)d_in[1];
    const float* state2  = (const float*)d_in[2];
    const float* ln1_w   = (const float*)d_in[3];
    const float* ln1_b   = (const float*)d_in[4];
    const float* tmx     = (const float*)d_in[5];
    const float* tmaa    = (const float*)d_in[6];
    const float* maa_w1  = (const float*)d_in[7];
    const float* maa_w2  = (const float*)d_in[8];
    const float* tdec    = (const float*)d_in[9];
    const float* tfirst  = (const float*)d_in[10];
    const float* dw1     = (const float*)d_in[11];
    const float* dw2     = (const float*)d_in[12];
    const float* Wr      = (const float*)d_in[13];
    const float* Wk      = (const float*)d_in[14];
    const float* Wv      = (const float*)d_in[15];
    const float* Wg      = (const float*)d_in[16];
    const float* Wo      = (const float*)d_in[17];
    const float* lnx_w   = (const float*)d_in[18];
    const float* lnx_b   = (const float*)d_in[19];
    float* out = (float*)d_out;

    k123<<<NB123, 256>>>(x, state1, ln1_w, ln1_b, tmx, tmaa, maa_w1, maa_w2, out);
    launch_pdl(k4_gemv4, dim3(2064), dim3(256), Wr, Wk, Wv, Wg, dw1);
    launch_pdl(k5_heads, dim3(64), dim3(256), state2, dw2, tdec, tfirst, lnx_w, lnx_b, out);
    launch_pdl(k6_out, dim3(512), dim3(256), Wo, x, out);
}

// round 13
// speedup vs baseline: 1.2028x; 1.2028x over previous
#include <cuda_runtime.h>
#include <stdint.h>
#include <math.h>

#define H   4096
#define HS  64
#define NH  64
#define TM  64
#define TD  128
#define EPS 1e-5f
#define CHUNK 256              // floats per row-chunk (1KB/row-chunk)
#define NCH   (H / CHUNK)      // 16 chunks
#define NSTG  3

// ---------------- scratch ----------------
__device__ __align__(16) float g_xl[H];
__device__ __align__(16) float g_sx[H];
__device__ __align__(16) float g_xm[H];
__device__ __align__(16) float g_y320[5 * TM];
__device__ __align__(16) float g_mix[5 * H];
__device__ __align__(16) float g_r[H];
__device__ __align__(16) float g_k[H];
__device__ __align__(16) float g_v[H];
__device__ __align__(16) float g_g[H];
__device__ __align__(16) float g_z128[TD];
__device__ __align__(16) float g_og[H];

__device__ __forceinline__ uint32_t smem_u32(const void* p) {
    return (uint32_t)__cvta_generic_to_shared(p);
}
__device__ __forceinline__ void cp16(uint32_t d, const void* s) {
    asm volatile("cp.async.cg.shared.global [%0], [%1], 16;" :: "r"(d), "l"(s));
}
__device__ __forceinline__ void cp_commit() {
    asm volatile("cp.async.commit_group;" ::: "memory");
}
template <int N>
__device__ __forceinline__ void cp_wait() {
    asm volatile("cp.async.wait_group %0;" :: "n"(N) : "memory");
}

// ---------------- K1: LN(x), sx, xm, zero accumulators ----------------
__global__ void k1_ln(const float* __restrict__ x,
                      const float* __restrict__ state1,
                      const float* __restrict__ ln1w,
                      const float* __restrict__ ln1b,
                      const float* __restrict__ tmx,
                      float* __restrict__ out) {
    cudaTriggerProgrammaticLaunchCompletion();   // let k2 launch + stage w1 now
    __shared__ float ssum[32], ssq[32];
    int tid = threadIdx.x;              // 1024 threads
    float vals[4];
    float s = 0.f, q = 0.f;
#pragma unroll
    for (int i = 0; i < 4; i++) {
        float v = x[tid + i * 1024];
        vals[i] = v; s += v; q += v * v;
    }
    for (int o = 16; o; o >>= 1) { s += __shfl_down_sync(~0u, s, o); q += __shfl_down_sync(~0u, q, o); }
    if ((tid & 31) == 0) { ssum[tid >> 5] = s; ssq[tid >> 5] = q; }
    __syncthreads();
    if (tid < 32) {
        float a = ssum[tid], b = ssq[tid];
        for (int o = 16; o; o >>= 1) { a += __shfl_down_sync(~0u, a, o); b += __shfl_down_sync(~0u, b, o); }
        if (tid == 0) { ssum[0] = a; ssq[0] = b; }
    }
    __syncthreads();
    float mu = ssum[0] * (1.f / H);
    float var = ssq[0] * (1.f / H) - mu * mu;
    float inv = rsqrtf(var + EPS);
#pragma unroll
    for (int i = 0; i < 4; i++) {
        int idx = tid + i * 1024;
        float xl = (vals[i] - mu) * inv * ln1w[idx] + ln1b[idx];
        g_xl[idx] = xl;
        out[H + idx] = xl;                       // output #2: xl
        float sx = state1[idx] - xl;
        g_sx[idx] = sx;
        g_xm[idx] = xl + sx * tmx[idx];
    }
    if (tid < 5 * TM) g_y320[tid] = 0.f;
    if (tid < TD)     g_z128[tid] = 0.f;
}

// ---------------- K2: y320 = xm @ maa_w1 (4096 x 320), 128 blocks x 320 ----------------
__global__ void __launch_bounds__(320) k2_maa_down(const float* __restrict__ w1) {
    __shared__ float sw1[32 * 320];   // 40KB tile
    __shared__ float sxm[32];
    int tid = threadIdx.x;
    int j0 = blockIdx.x * 32;
    // pre-sync: stage this block's w1 tile (input-independent)
    uint32_t sb = smem_u32(sw1);
    const float4* src = (const float4*)(w1 + (size_t)j0 * 320);
#pragma unroll
    for (int i = 0; i < 8; i++)       // 2560 float4 / 320 threads
        cp16(sb + (tid + i * 320) * 16, src + tid + i * 320);
    cp_commit();
    cudaTriggerProgrammaticLaunchCompletion();
    cudaGridDependencySynchronize();
    if (tid < 32) sxm[tid] = g_xm[j0 + tid];
    cp_wait<0>();
    __syncthreads();
    float acc = 0.f;
#pragma unroll 8
    for (int j = 0; j < 32; j++)
        acc += sxm[j] * sw1[j * 320 + tid];
    atomicAdd(&g_y320[tid], acc);
}

// ---------------- K3: mixes = xl + sx*(lora_up + time_maa), 160 blocks x 128 ----------------
__global__ void __launch_bounds__(128) k3_maa_up(const float* __restrict__ w2,
                                                 const float* __restrict__ tmaa) {
    __shared__ float sw2[TM * 128];   // 32KB tile: 64 rows x 128 floats
    __shared__ float ty[TM];
    int tid = threadIdx.x;
    int b = blockIdx.x;
    int f = b >> 5;                   // 32 blocks per mix
    int h0 = (b & 31) * 128;
    // pre-sync: stage w2 tile (input-independent)
    uint32_t sb = smem_u32(sw2);
#pragma unroll
    for (int i = 0; i < 16; i++) {
        int idx = tid + i * 128;      // float4 slot 0..2047
        int t = idx >> 5, c = idx & 31;
        cp16(sb + idx * 16,
             (const float4*)(w2 + (size_t)f * TM * H + (size_t)t * H + h0) + c);
    }
    cp_commit();
    cudaTriggerProgrammaticLaunchCompletion();
    cudaGridDependencySynchronize();
    if (tid < TM) ty[tid] = tanhf(g_y320[f * TM + tid]);
    cp_wait<0>();
    __syncthreads();
    int h = h0 + tid;
    float acc = 0.f;
#pragma unroll
    for (int t = 0; t < TM; t++) acc += ty[t] * sw2[t * 128 + tid];
    g_mix[f * H + h] = g_xl[h] + g_sx[h] * (acc + tmaa[f * H + h]);
}

// ---------------- K4: 4 big GEMVs (per-warp barrier-free cp.async pipeline) ----------------
__global__ void __launch_bounds__(256) k4_gemv4(
        const float* __restrict__ Wr, const float* __restrict__ Wk,
        const float* __restrict__ Wv, const float* __restrict__ Wg,
        const float* __restrict__ dw1) {
    __shared__ float sv[H];                        // 16KB vector tile
    __shared__ float stage[NSTG][8][CHUNK];        // 3 x 8KB, per-warp slices
    __shared__ float sh[256];

    if (blockIdx.x >= 2048) {
        cudaTriggerProgrammaticLaunchCompletion();
        cudaGridDependencySynchronize();
        // decay stage 1: z128 = mw @ decay_w1 (4096 x 128), 16 blocks x 256 rows
        int bb = blockIdx.x - 2048;
        int j0 = bb * 256;
        int t = threadIdx.x & 127;
        int sub = threadIdx.x >> 7;
        float acc = 0.f;
        for (int j = j0 + sub; j < j0 + 256; j += 2)
            acc += g_mix[j] * dw1[j * TD + t];   // mw = mix[0]
        sh[threadIdx.x] = acc;
        __syncthreads();
        if (sub == 0) atomicAdd(&g_z128[t], sh[t] + sh[t + 128]);
        return;
    }

    int mat = blockIdx.x >> 9;                   // 512 blocks per matrix
    const float* W; const float* vec;
    if (mat == 0)      { W = Wr; vec = g_mix + 3 * H; }   // r <- mr
    else if (mat == 1) { W = Wk; vec = g_mix + 1 * H; }   // k <- mk
    else if (mat == 2) { W = Wv; vec = g_mix + 2 * H; }   // v <- mv
    else               { W = Wg; vec = g_mix + 4 * H; }   // g <- mg

    int tid = threadIdx.x;
    int warp = tid >> 5, lane = tid & 31;
    int row = (blockIdx.x & 511) * 8 + warp;
    const float* Wrow = W + (size_t)row * H;     // this warp's row

    uint32_t sdst[NSTG];
#pragma unroll
    for (int s = 0; s < NSTG; s++)
        sdst[s] = smem_u32(&stage[s][warp][0]) + lane * 16;

    // prologue: weights are input-independent — issue BEFORE the PDL sync
#pragma unroll
    for (int s = 0; s < NSTG; s++) {
        const float4* src = (const float4*)(Wrow + s * CHUNK);
        cp16(sdst[s],            src + lane);
        cp16(sdst[s] + 32 * 16,  src + lane + 32);
        cp_commit();
    }
    cudaTriggerProgrammaticLaunchCompletion();   // let k5 (and transitively k6) launch

    cudaGridDependencySynchronize();

    // stage the vector (depends on K3); one barrier total
    {
        const float4* V4 = (const float4*)vec;
        float4* S4 = (float4*)sv;
#pragma unroll
        for (int i = 0; i < 4; i++)
            S4[tid + i * 256] = V4[tid + i * 256];
    }
    __syncthreads();

    float acc = 0.f;
#pragma unroll
    for (int c = 0; c < NCH; c++) {
        if (c < NCH - 2)       cp_wait<NSTG - 1>();
        else if (c == NCH - 2) cp_wait<1>();
        else                   cp_wait<0>();
        // lane reads exactly the slots it issued — no barrier needed
        const float4* SB = (const float4*)&stage[c % NSTG][warp][0];
        const float4* SV = (const float4*)&sv[c * CHUNK];
        float4 w0 = SB[lane],       u0 = SV[lane];
        float4 w1_ = SB[lane + 32], u1 = SV[lane + 32];
        acc += w0.x * u0.x + w0.y * u0.y + w0.z * u0.z + w0.w * u0.w;
        acc += w1_.x * u1.x + w1_.y * u1.y + w1_.z * u1.z + w1_.w * u1.w;
        if (c + NSTG < NCH) {
            const float4* src = (const float4*)(Wrow + (c + NSTG) * CHUNK);
            cp16(sdst[c % NSTG],           src + lane);
            cp16(sdst[c % NSTG] + 32 * 16, src + lane + 32);
            cp_commit();
        }
    }

    for (int o = 16; o; o >>= 1) acc += __shfl_down_sync(~0u, acc, o);
    if (lane == 0) {
        if (mat == 0)      g_r[row] = acc;
        else if (mat == 1) g_k[row] = acc;
        else if (mat == 2) g_v[row] = acc;
        else               g_g[row] = acc / (1.f + expf(-acc)); // silu
    }
}

// ---------------- K5: per-head decay/wkv/state/norm (256 threads/head) ----------------
__global__ void k5_heads(const float* __restrict__ state2,
                         const float* __restrict__ dw2,
                         const float* __restrict__ tdec,
                         const float* __restrict__ tfirst,
                         const float* __restrict__ lnxw,
                         const float* __restrict__ lnxb,
                         float* __restrict__ out) {
    cudaTriggerProgrammaticLaunchCompletion();   // let k6 launch + stage Wo during k4 tail/k5
    cudaGridDependencySynchronize();
    int h = blockIdx.x;                 // 64 heads
    int tid = threadIdx.x;              // 256 threads
    int j = tid & 63;                   // column within head
    int p = tid >> 6;                   // 0..3 partition
    const float* s2 = state2 + (size_t)h * HS * HS;

    __shared__ float tz[TD], sr[HS], sk[HS], std_[HS], red[HS];
    __shared__ float part[4][HS];

    if (tid < TD) tz[tid] = tanhf(g_z128[tid]);
    __syncthreads();

    int gi = h * HS + j;

    float dacc = 0.f;
#pragma unroll
    for (int t = p * 32; t < p * 32 + 32; t++)
        dacc += tz[t] * dw2[(size_t)t * H + gi];
    part[p][j] = dacc;
    __syncthreads();
    if (p == 0) {
        float d = part[0][j] + part[1][j] + part[2][j] + part[3][j] + tdec[gi];
        d = fminf(fmaxf(d, -9.72f), 2.27f);
        std_[j] = expf(-expf(d));
        float rs = g_r[gi], ks = g_k[gi];
        sr[j] = rs; sk[j] = ks;
        red[j] = rs * ks * tfirst[gi];
    }
    __syncthreads();

    float a = 0.f;
#pragma unroll
    for (int t = 0; t < HS; t++) a += red[t];   // broadcast reads

    float vs = g_v[gi];
    float* s2o = out + 2 * H + (size_t)h * HS * HS;   // output #3: state2_out
    float acc2 = 0.f;
#pragma unroll
    for (int i = p * 16; i < p * 16 + 16; i++) {
        float s2v = s2[i * HS + j];
        acc2 += sr[i] * s2v;
        s2o[i * HS + j] = sk[i] * vs + s2v * std_[i];
    }
    part[p][j] = acc2;
    __syncthreads();

    if (p == 0) {
        float oj = a * vs + part[0][j] + part[1][j] + part[2][j] + part[3][j];
        red[j] = oj;
    }
    __syncthreads();
    if (p == 0) {
        float s = 0.f, q = 0.f;
#pragma unroll
        for (int t = 0; t < HS; t++) { float u = red[t]; s += u; q += u * u; }
        float mu = s * (1.f / HS);
        float var = q * (1.f / HS) - mu * mu;
        float nj = (red[j] - mu) * rsqrtf(var + EPS);
        g_og[gi] = (nj * lnxw[gi] + lnxb[gi]) * g_g[gi];
    }
}

// ---------------- K6: out = x + og @ Wo.T (per-warp barrier-free pipeline) ----------------
__global__ void __launch_bounds__(256) k6_out(const float* __restrict__ Wo,
                                              const float* __restrict__ x,
                                              float* __restrict__ out) {
    __shared__ float sv[H];
    __shared__ float stage[NSTG][8][CHUNK];
    int tid = threadIdx.x;
    int warp = tid >> 5, lane = tid & 31;
    int row = blockIdx.x * 8 + warp;
    const float* Wrow = Wo + (size_t)row * H;

    uint32_t sdst[NSTG];
#pragma unroll
    for (int s = 0; s < NSTG; s++)
        sdst[s] = smem_u32(&stage[s][warp][0]) + lane * 16;

#pragma unroll
    for (int s = 0; s < NSTG; s++) {
        const float4* src = (const float4*)(Wrow + s * CHUNK);
        cp16(sdst[s],            src + lane);
        cp16(sdst[s] + 32 * 16,  src + lane + 32);
        cp_commit();
    }

    cudaGridDependencySynchronize();

    {
        const float4* V4 = (const float4*)g_og;
        float4* S4 = (float4*)sv;
#pragma unroll
        for (int i = 0; i < 4; i++)
            S4[tid + i * 256] = V4[tid + i * 256];
    }
    __syncthreads();

    float acc = 0.f;
#pragma unroll
    for (int c = 0; c < NCH; c++) {
        if (c < NCH - 2)       cp_wait<NSTG - 1>();
        else if (c == NCH - 2) cp_wait<1>();
        else                   cp_wait<0>();
        const float4* SB = (const float4*)&stage[c % NSTG][warp][0];
        const float4* SV = (const float4*)&sv[c * CHUNK];
        float4 w0 = SB[lane],       u0 = SV[lane];
        float4 w1_ = SB[lane + 32], u1 = SV[lane + 32];
        acc += w0.x * u0.x + w0.y * u0.y + w0.z * u0.z + w0.w * u0.w;
        acc += w1_.x * u1.x + w1_.y * u1.y + w1_.z * u1.z + w1_.w * u1.w;
        if (c + NSTG < NCH) {
            const float4* src = (const float4*)(Wrow + (c + NSTG) * CHUNK);
            cp16(sdst[c % NSTG],           src + lane);
            cp16(sdst[c % NSTG] + 32 * 16, src + lane + 32);
            cp_commit();
        }
    }

    for (int o = 16; o; o >>= 1) acc += __shfl_down_sync(~0u, acc, o);
    if (lane == 0) out[row] = x[row] + acc;
}

// ---------------- launch helpers ----------------
template <typename... Args>
static void launch_pdl(void (*kern)(Args...), dim3 grid, dim3 block, Args... args) {
    cudaLaunchConfig_t cfg = {};
    cfg.gridDim = grid;
    cfg.blockDim = block;
    cfg.dynamicSmemBytes = 0;
    cfg.stream = 0;
    cudaLaunchAttribute attr[1];
    attr[0].id = cudaLaunchAttributeProgrammaticStreamSerialization;
    attr[0].val.programmaticStreamSerializationAllowed = 1;
    cfg.attrs = attr;
    cfg.numAttrs = 1;
    cudaLaunchKernelEx(&cfg, kern, args...);
}

extern "C" void kernel_launch(void* const* d_in, const int* in_sizes, int n_in,
                              void* d_out, int out_size) {
    const float* x       = (const float*)d_in[0];
    const float* state1  = (const float*)d_in[1];
    const float* state2  = (const float*)d_in[2];
    const float* ln1_w   = (const float*)d_in[3];
    const float* ln1_b   = (const float*)d_in[4];
    const float* tmx     = (const float*)d_in[5];
    const float* tmaa    = (const float*)d_in[6];
    const float* maa_w1  = (const float*)d_in[7];
    const float* maa_w2  = (const float*)d_in[8];
    const float* tdec    = (const float*)d_in[9];
    const float* tfirst  = (const float*)d_in[10];
    const float* dw1     = (const float*)d_in[11];
    const float* dw2     = (const float*)d_in[12];
    const float* Wr      = (const float*)d_in[13];
    const float* Wk      = (const float*)d_in[14];
    const float* Wv      = (const float*)d_in[15];
    const float* Wg      = (const float*)d_in[16];
    const float* Wo      = (const float*)d_in[17];
    const float* lnx_w   = (const float*)d_in[18];
    const float* lnx_b   = (const float*)d_in[19];
    float* out = (float*)d_out;

    k1_ln<<<1, 1024>>>(x, state1, ln1_w, ln1_b, tmx, out);
    launch_pdl(k2_maa_down, dim3(128), dim3(320), maa_w1);
    launch_pdl(k3_maa_up, dim3(160), dim3(128), maa_w2, tmaa);
    launch_pdl(k4_gemv4, dim3(2064), dim3(256), Wr, Wk, Wv, Wg, dw1);
    launch_pdl(k5_heads, dim3(64), dim3(256), state2, dw2, tdec, tfirst, lnx_w, lnx_b, out);
    launch_pdl(k6_out, dim3(512), dim3(256), Wo, x, out);
}